// round 12
// baseline (speedup 1.0000x reference)
#include <cuda_runtime.h>
#include <cuda_bf16.h>
#include <math_constants.h>

// Problem constants
#define BATCH   2
#define NPTS    8192
#define KNN     11        // k+1 including self
#define LEN_IN  66        // 3*11 + 3*10 + 3
#define TPB     128
#define NGROUP  8         // split-K over candidates
#define QPB     (TPB / NGROUP)        // 16 queries per block
#define GRANGE  (NPTS / NGROUP)       // 1024 candidates per group
#define CHUNK   128                   // candidates per group per smem iteration
#define NITER   (GRANGE / CHUNK)      // 8
#define BUCK_CAP    16                // per-thread staging slots
#define BUCK_FLUSH  8                 // flush when any lane reaches this

// Collapsed weights (device scratch; no allocations allowed)
__device__ float g_W12[LEN_IN * 16];
__device__ float g_Wc [LEN_IN * 6];
__device__ float g_bc [6];

// ---------------------------------------------------------------------------
// Prologue: collapse W1@W2@W3 and the bias chain (tiny, one block).
// The reference MLP has no activation functions, so the whole head is affine:
//   pred = feats @ (W1@W2@W3) + ((b1@W2 + b2)@W3 + b3)
// ---------------------------------------------------------------------------
__global__ void combine_weights_kernel(const float* __restrict__ W1,
                                       const float* __restrict__ b1,
                                       const float* __restrict__ W2,
                                       const float* __restrict__ b2,
                                       const float* __restrict__ W3,
                                       const float* __restrict__ b3)
{
    int t = threadIdx.x;
    // W12 = W1[66,32] @ W2[32,16]
    for (int e = t; e < LEN_IN * 16; e += blockDim.x) {
        int r = e / 16, c = e % 16;
        float s = 0.f;
        for (int k = 0; k < 32; ++k) s += W1[r * 32 + k] * W2[k * 16 + c];
        g_W12[e] = s;
    }
    __syncthreads();
    // Wc = W12[66,16] @ W3[16,6]
    for (int e = t; e < LEN_IN * 6; e += blockDim.x) {
        int r = e / 6, c = e % 6;
        float s = 0.f;
        for (int k = 0; k < 16; ++k) s += g_W12[r * 16 + k] * W3[k * 6 + c];
        g_Wc[e] = s;
    }
    // bc = ((b1@W2)+b2)@W3 + b3
    if (t < 6) {
        float s = b3[t];
        for (int k = 0; k < 16; ++k) {
            float tb = b2[k];
            for (int m = 0; m < 32; ++m) tb += b1[m] * W2[m * 16 + k];
            s += tb * W3[k * 6 + t];
        }
        g_bc[t] = s;
    }
}

// ---------------------------------------------------------------------------
// Main fused kernel: split-K brute-force kNN (top-11 by d2) with staged
// inserts (conflict-free slot-major buckets) + exact 8-way merge + gather +
// collapsed linear head.
//   Block = 16 queries x 8 candidate groups (128 threads).
//   Thread (warp w, lane l): group = 2w + (l>>4), query = l & 15.
//   s_md/s_mi alias s_tile (tile is dead once the scan finishes).
// ---------------------------------------------------------------------------
__global__ void __launch_bounds__(TPB, 6)
knn_mlp_kernel(const float* __restrict__ pos,
               const float* __restrict__ vel,
               const float* __restrict__ initc,
               float* __restrict__ out)
{
    __shared__ float4 s_tile[NGROUP * CHUNK];      // candidate chunks (16KB)
    __shared__ float  s_bdk[BUCK_CAP * TPB];       // staged d2, slot-major (8KB)
    __shared__ int    s_bik[BUCK_CAP * TPB];       // staged idx, slot-major (8KB)
    __shared__ float  s_Wc[LEN_IN * 6];
    __shared__ float  s_bc[6];

    // Aliased onto s_tile after the scan (11.3KB <= 16KB):
    float* const s_md = reinterpret_cast<float*>(s_tile);            // TPB*KNN
    int*   const s_mi = reinterpret_cast<int*>(s_tile) + TPB * KNN;  // TPB*KNN

    const int tid  = threadIdx.x;
    const int lane = tid & 31;
    const int warp = tid >> 5;
    const int grp  = (warp << 1) | (lane >> 4);    // 0..7
    const int qloc = lane & (QPB - 1);             // query within block
    const int q    = blockIdx.x * QPB + qloc;      // global query id
    const int bb   = q >> 13;                      // q / 8192 (batch)
    const int i    = q & (NPTS - 1);
    const int pub  = grp * QPB + qloc;             // publish slot

    const float* __restrict__ bpos = pos + (size_t)bb * NPTS * 3;
    const float* __restrict__ bvel = vel + (size_t)bb * NPTS * 3;

    for (int t = tid; t < LEN_IN * 6; t += TPB) s_Wc[t] = g_Wc[t];
    if (tid < 6) s_bc[tid] = g_bc[tid];

    // Query point; sq computed with the SAME op sequence as the tile loader so
    // the self-distance is exactly 0 (round-5 passing recipe, unchanged).
    const float qx = bpos[i * 3 + 0];
    const float qy = bpos[i * 3 + 1];
    const float qz = bpos[i * 3 + 2];
    float qs = qx * qx; qs = fmaf(qy, qy, qs); qs = fmaf(qz, qz, qs);

    // Per-group sorted top-11 (ascending), register-resident.
    float bd[KNN];
    int   bi[KNN];
#pragma unroll
    for (int k = 0; k < KNN; ++k) { bd[k] = CUDART_INF_F; bi[k] = 0; }

    int   cnt = 0;
    float tau = CUDART_INF_F;

    const float4* __restrict__ mytile = s_tile + grp * CHUNK;

    for (int it = 0; it < NITER; ++it) {
        __syncthreads();
        // Cooperative load of all groups' chunks: (x,y,z,sq)
        for (int t = tid; t < NGROUP * CHUNK; t += TPB) {
            const int g  = t >> 7;                        // t / CHUNK
            const int r  = t & (CHUNK - 1);
            const int j  = g * GRANGE + it * CHUNK + r;   // global candidate id
            const float x = bpos[j * 3 + 0];
            const float y = bpos[j * 3 + 1];
            const float z = bpos[j * 3 + 2];
            float s = x * x; s = fmaf(y, y, s); s = fmaf(z, z, s);
            s_tile[t] = make_float4(x, y, z, s);
        }
        __syncthreads();

        const int idxbase = grp * GRANGE + it * CHUNK;
        for (int tb = 0; tb < CHUNK; tb += 4) {
#pragma unroll
            for (int v = 0; v < 4; ++v) {
                const int t = tb + v;
                const float4 p = mytile[t];
                float d = qx * p.x; d = fmaf(qy, p.y, d); d = fmaf(qz, p.z, d);
                const float d2 = fmaf(-2.0f, d, qs + p.w);
                // Cheap staged append; slot-major layout -> bank = tid%32,
                // conflict-free for any mix of per-lane cnt values.
                if (d2 < tau) {
                    s_bdk[cnt * TPB + tid] = d2;
                    s_bik[cnt * TPB + tid] = idxbase + t;
                    ++cnt;
                }
            }
            // Warp-coherent flush when any lane's bucket reaches threshold.
            // (<=4 appends between checks; capacity 16 is safe.)
            if (__ballot_sync(0xFFFFFFFFu, cnt >= BUCK_FLUSH)) {
                // Replay staged items in scan order through the EXACT serial
                // strict-'<' chain (round-5/9 passing semantics). Replaying a
                // superset of qualifying candidates is a no-op for the
                // non-qualifying ones, so stale-tau staging is bit-exact.
                for (int u = 0; u < cnt; ++u) {
                    float dv = s_bdk[u * TPB + tid];
                    if (dv < bd[KNN - 1]) {
                        int id = s_bik[u * TPB + tid];
#pragma unroll
                        for (int k = 0; k < KNN; ++k) {
                            if (dv < bd[k]) {
                                float td = bd[k]; bd[k] = dv; dv = td;
                                int   ti = bi[k]; bi[k] = id; id = ti;
                            }
                        }
                    }
                }
                cnt = 0;
                tau = bd[KNN - 1];
            }
        }
    }
    // Flush remaining staged candidates.
    for (int u = 0; u < cnt; ++u) {
        float dv = s_bdk[u * TPB + tid];
        if (dv < bd[KNN - 1]) {
            int id = s_bik[u * TPB + tid];
#pragma unroll
            for (int k = 0; k < KNN; ++k) {
                if (dv < bd[k]) {
                    float td = bd[k]; bd[k] = dv; dv = td;
                    int   ti = bi[k]; bi[k] = id; id = ti;
                }
            }
        }
    }

    // All warps must be done reading s_tile before we overwrite it (aliased).
    __syncthreads();

    // Publish partial lists (slot = grp*QPB + qloc).
#pragma unroll
    for (int k = 0; k < KNN; ++k) {
        s_md[pub * KNN + k] = bd[k];
        s_mi[pub * KNN + k] = bi[k];
    }
    __syncthreads();

    // Threads 0..15 merge their query's eight sorted lists sequentially.
    // On equal d2 the lower group wins (its indices are all lower) —
    // same tie rule as the passing round-9/11 merges.
    if (tid < QPB) {
        float cd[KNN]; int ci[KNN];
        {
            const int base = (0 * QPB + tid) * KNN;
#pragma unroll
            for (int k = 0; k < KNN; ++k) { cd[k] = s_md[base + k]; ci[k] = s_mi[base + k]; }
        }
        for (int g = 1; g < NGROUP; ++g) {
            const int base = (g * QPB + tid) * KNN;
            float nd[KNN]; int ni[KNN];
            int ia = 0, ib = 0;
#pragma unroll
            for (int k = 0; k < KNN; ++k) {
                const float da = cd[ia];
                const float db = s_md[base + ib];
                if (da <= db) { nd[k] = da; ni[k] = ci[ia]; ++ia; }
                else          { nd[k] = db; ni[k] = s_mi[base + ib]; ++ib; }
            }
#pragma unroll
            for (int k = 0; k < KNN; ++k) { cd[k] = nd[k]; ci[k] = ni[k]; }
        }

        // ---- gather features and apply collapsed linear head ----
        const int qq = blockIdx.x * QPB + tid;
        const int bb2 = qq >> 13;
        const int ii  = qq & (NPTS - 1);
        const float* __restrict__ bpos2 = pos + (size_t)bb2 * NPTS * 3;
        const float* __restrict__ bvel2 = vel + (size_t)bb2 * NPTS * 3;
        const float qx2 = bpos2[ii * 3 + 0];
        const float qy2 = bpos2[ii * 3 + 1];
        const float qz2 = bpos2[ii * 3 + 2];

        float acc[6];
#pragma unroll
        for (int c = 0; c < 6; ++c) acc[c] = s_bc[c];

        // rows 0..32: neighbor velocities (incl. self, rank order)
#pragma unroll
        for (int r = 0; r < KNN; ++r) {
            const int j = ci[r];
            const float vx = bvel2[j * 3 + 0];
            const float vy = bvel2[j * 3 + 1];
            const float vz = bvel2[j * 3 + 2];
            const int row = 3 * r;
#pragma unroll
            for (int c = 0; c < 6; ++c) {
                acc[c] = fmaf(vx, s_Wc[(row + 0) * 6 + c], acc[c]);
                acc[c] = fmaf(vy, s_Wc[(row + 1) * 6 + c], acc[c]);
                acc[c] = fmaf(vz, s_Wc[(row + 2) * 6 + c], acc[c]);
            }
        }
        // rows 33..62: neighbor position offsets (excl. self)
#pragma unroll
        for (int r = 1; r < KNN; ++r) {
            const int j = ci[r];
            const float ox = bpos2[j * 3 + 0] - qx2;
            const float oy = bpos2[j * 3 + 1] - qy2;
            const float oz = bpos2[j * 3 + 2] - qz2;
            const int row = 33 + 3 * (r - 1);
#pragma unroll
            for (int c = 0; c < 6; ++c) {
                acc[c] = fmaf(ox, s_Wc[(row + 0) * 6 + c], acc[c]);
                acc[c] = fmaf(oy, s_Wc[(row + 1) * 6 + c], acc[c]);
                acc[c] = fmaf(oz, s_Wc[(row + 2) * 6 + c], acc[c]);
            }
        }
        // rows 63..65: init_config
        {
            const float i0 = initc[bb2 * 3 + 0];
            const float i1 = initc[bb2 * 3 + 1];
            const float i2 = initc[bb2 * 3 + 2];
#pragma unroll
            for (int c = 0; c < 6; ++c) {
                acc[c] = fmaf(i0, s_Wc[63 * 6 + c], acc[c]);
                acc[c] = fmaf(i1, s_Wc[64 * 6 + c], acc[c]);
                acc[c] = fmaf(i2, s_Wc[65 * 6 + c], acc[c]);
            }
        }

        float* o = out + (size_t)qq * 6;
        o[0] = acc[0] + qx2;
        o[1] = acc[1] + qy2;
        o[2] = acc[2] + qz2;
        o[3] = acc[3];
        o[4] = acc[4];
        o[5] = acc[5];
    }
}

// ---------------------------------------------------------------------------
extern "C" void kernel_launch(void* const* d_in, const int* in_sizes, int n_in,
                              void* d_out, int out_size)
{
    const float* position = (const float*)d_in[0];
    const float* velocity = (const float*)d_in[1];
    const float* initcfg  = (const float*)d_in[2];
    const float* W1 = (const float*)d_in[3];
    const float* b1 = (const float*)d_in[4];
    const float* W2 = (const float*)d_in[5];
    const float* b2 = (const float*)d_in[6];
    const float* W3 = (const float*)d_in[7];
    const float* b3 = (const float*)d_in[8];
    float* out = (float*)d_out;

    combine_weights_kernel<<<1, 256>>>(W1, b1, W2, b2, W3, b3);

    const int total = BATCH * NPTS;           // 16384 queries
    knn_mlp_kernel<<<total / QPB, TPB>>>(position, velocity, initcfg, out);
}

// round 14
// speedup vs baseline: 1.8180x; 1.8180x over previous
#include <cuda_runtime.h>
#include <cuda_bf16.h>
#include <math_constants.h>

// Problem constants
#define BATCH   2
#define NPTS    8192
#define KNN     11        // k+1 including self
#define LEN_IN  66        // 3*11 + 3*10 + 3
#define TPB     128
#define NGROUP  4         // split-K over candidates
#define QPB     (TPB / NGROUP)        // 32 queries per block
#define GRANGE  (NPTS / NGROUP)       // 2048 candidates per group
#define CHUNK   256                   // candidates per group per smem iteration
#define NPAIR   (CHUNK / 2)           // 128 candidate pairs per group chunk
#define NITER   (GRANGE / CHUNK)      // 8
#define BUCK_CAP    16                // per-thread staging slots
#define BUCK_FLUSH  8                 // flush when any lane reaches this

typedef unsigned long long ull;

// Collapsed weights (device scratch; no allocations allowed)
__device__ float g_W12[LEN_IN * 16];
__device__ float g_Wc [LEN_IN * 6];
__device__ float g_bc [6];

// ---- packed f32x2 helpers (each lane is bit-identical to the scalar op) ----
__device__ __forceinline__ ull mul2(ull a, ull b) {
    ull r; asm("mul.rn.f32x2 %0, %1, %2;" : "=l"(r) : "l"(a), "l"(b)); return r;
}
__device__ __forceinline__ ull add2(ull a, ull b) {
    ull r; asm("add.rn.f32x2 %0, %1, %2;" : "=l"(r) : "l"(a), "l"(b)); return r;
}
__device__ __forceinline__ ull fma2(ull a, ull b, ull c) {
    ull r; asm("fma.rn.f32x2 %0, %1, %2, %3;" : "=l"(r) : "l"(a), "l"(b), "l"(c)); return r;
}
__device__ __forceinline__ ull pack2(float lo, float hi) {
    return (ull)__float_as_uint(lo) | ((ull)__float_as_uint(hi) << 32);
}
__device__ __forceinline__ void unpack2(ull v, float& lo, float& hi) {
    asm("mov.b64 {%0, %1}, %2;" : "=f"(lo), "=f"(hi) : "l"(v));
}

// ---------------------------------------------------------------------------
// Prologue: collapse W1@W2@W3 and the bias chain (tiny, one block).
// The reference MLP has no activation functions, so the whole head is affine:
//   pred = feats @ (W1@W2@W3) + ((b1@W2 + b2)@W3 + b3)
// ---------------------------------------------------------------------------
__global__ void combine_weights_kernel(const float* __restrict__ W1,
                                       const float* __restrict__ b1,
                                       const float* __restrict__ W2,
                                       const float* __restrict__ b2,
                                       const float* __restrict__ W3,
                                       const float* __restrict__ b3)
{
    int t = threadIdx.x;
    // W12 = W1[66,32] @ W2[32,16]
    for (int e = t; e < LEN_IN * 16; e += blockDim.x) {
        int r = e / 16, c = e % 16;
        float s = 0.f;
        for (int k = 0; k < 32; ++k) s += W1[r * 32 + k] * W2[k * 16 + c];
        g_W12[e] = s;
    }
    __syncthreads();
    // Wc = W12[66,16] @ W3[16,6]
    for (int e = t; e < LEN_IN * 6; e += blockDim.x) {
        int r = e / 6, c = e % 6;
        float s = 0.f;
        for (int k = 0; k < 16; ++k) s += g_W12[r * 16 + k] * W3[k * 6 + c];
        g_Wc[e] = s;
    }
    // bc = ((b1@W2)+b2)@W3 + b3
    if (t < 6) {
        float s = b3[t];
        for (int k = 0; k < 16; ++k) {
            float tb = b2[k];
            for (int m = 0; m < 32; ++m) tb += b1[m] * W2[m * 16 + k];
            s += tb * W3[k * 6 + t];
        }
        g_bc[t] = s;
    }
}

// ---------------------------------------------------------------------------
// Main fused kernel: split-K brute-force kNN (top-11 by d2) with packed-pair
// distance math, staged inserts (slot-major buckets) + exact 4-way merge +
// gather + collapsed linear head. Structure identical to the round-11 kernel
// (197us); only the scan arithmetic is packed f32x2 (bit-identical lanes).
//   Block = 32 queries x 4 candidate groups (128 threads).
// ---------------------------------------------------------------------------
__global__ void __launch_bounds__(TPB)
knn_mlp_kernel(const float* __restrict__ pos,
               const float* __restrict__ vel,
               const float* __restrict__ initc,
               float* __restrict__ out)
{
    // Tile in pair-packed SoA: sXY[p] = ((x0,x1),(y0,y1)), sZW[p] = ((z0,z1),(w0,w1))
    __shared__ ulonglong2 sXY[NGROUP * NPAIR];     // 8KB
    __shared__ ulonglong2 sZW[NGROUP * NPAIR];     // 8KB
    __shared__ float  s_bdk[BUCK_CAP * TPB];       // staged d2, slot-major (8KB)
    __shared__ int    s_bik[BUCK_CAP * TPB];       // staged idx, slot-major (8KB)
    __shared__ float  s_md[TPB * KNN];             // partial top-11 distances
    __shared__ int    s_mi[TPB * KNN];             // partial top-11 indices
    __shared__ float  s_Wc[LEN_IN * 6];
    __shared__ float  s_bc[6];

    const int tid  = threadIdx.x;
    const int grp  = tid >> 5;                     // 0..3  (== warp id)
    const int qloc = tid & (QPB - 1);              // query within block
    const int q    = blockIdx.x * QPB + qloc;      // global query id
    const int bb   = q >> 13;                      // q / 8192 (batch)
    const int i    = q & (NPTS - 1);

    const float* __restrict__ bpos = pos + (size_t)bb * NPTS * 3;
    const float* __restrict__ bvel = vel + (size_t)bb * NPTS * 3;

    for (int t = tid; t < LEN_IN * 6; t += TPB) s_Wc[t] = g_Wc[t];
    if (tid < 6) s_bc[tid] = g_bc[tid];

    // Query point; sq computed with the SAME op sequence as the tile loader so
    // the self-distance is exactly 0 (round-5 passing recipe, unchanged).
    const float qx = bpos[i * 3 + 0];
    const float qy = bpos[i * 3 + 1];
    const float qz = bpos[i * 3 + 2];
    float qs = qx * qx; qs = fmaf(qy, qy, qs); qs = fmaf(qz, qz, qs);

    // Packed query constants
    const ull qxx = pack2(qx, qx);
    const ull qyy = pack2(qy, qy);
    const ull qzz = pack2(qz, qz);
    const ull qss = pack2(qs, qs);
    const ull m22 = pack2(-2.0f, -2.0f);

    // Per-group sorted top-11 (ascending), register-resident.
    float bd[KNN];
    int   bi[KNN];
#pragma unroll
    for (int k = 0; k < KNN; ++k) { bd[k] = CUDART_INF_F; bi[k] = 0; }

    int   cnt = 0;
    float tau = CUDART_INF_F;

    const ulonglong2* __restrict__ myXY = sXY + grp * NPAIR;
    const ulonglong2* __restrict__ myZW = sZW + grp * NPAIR;

    for (int it = 0; it < NITER; ++it) {
        __syncthreads();
        // Cooperative load of all groups' chunks in pair-packed form.
        for (int t = tid; t < NGROUP * NPAIR; t += TPB) {
            const int g  = t >> 7;                        // t / NPAIR
            const int pr = t & (NPAIR - 1);
            const int j0 = g * GRANGE + it * CHUNK + 2 * pr;  // global cand id
            const float x0 = bpos[j0 * 3 + 0];
            const float y0 = bpos[j0 * 3 + 1];
            const float z0 = bpos[j0 * 3 + 2];
            const float x1 = bpos[j0 * 3 + 3];
            const float y1 = bpos[j0 * 3 + 4];
            const float z1 = bpos[j0 * 3 + 5];
            float s0 = x0 * x0; s0 = fmaf(y0, y0, s0); s0 = fmaf(z0, z0, s0);
            float s1 = x1 * x1; s1 = fmaf(y1, y1, s1); s1 = fmaf(z1, z1, s1);
            sXY[t] = make_ulonglong2(pack2(x0, x1), pack2(y0, y1));
            sZW[t] = make_ulonglong2(pack2(z0, z1), pack2(s0, s1));
        }
        __syncthreads();

        const int idxbase = grp * GRANGE + it * CHUNK;
        for (int ptb = 0; ptb < NPAIR; ptb += 4) {
#pragma unroll
            for (int v = 0; v < 4; ++v) {
                const int pt = ptb + v;
                const ulonglong2 xy = myXY[pt];
                const ulonglong2 zw = myZW[pt];
                // Packed distance: lanes identical to the scalar recipe
                // d = qx*x; d = fma(qy,y,d); d = fma(qz,z,d);
                // d2 = fma(-2, d, qs + sq)
                ull dd = mul2(qxx, xy.x);
                dd = fma2(qyy, xy.y, dd);
                dd = fma2(qzz, zw.x, dd);
                const ull tt = add2(qss, zw.y);
                const ull rr = fma2(m22, dd, tt);
                float d2lo, d2hi;
                unpack2(rr, d2lo, d2hi);
                // Stage in scan order: lo candidate first, then hi.
                if (d2lo < tau) {
                    s_bdk[cnt * TPB + tid] = d2lo;
                    s_bik[cnt * TPB + tid] = idxbase + 2 * pt;
                    ++cnt;
                }
                if (d2hi < tau) {
                    s_bdk[cnt * TPB + tid] = d2hi;
                    s_bik[cnt * TPB + tid] = idxbase + 2 * pt + 1;
                    ++cnt;
                }
            }
            // Warp-coherent flush when any lane's bucket reaches threshold.
            // (<=8 appends between checks; capacity 16 is safe.)
            if (__ballot_sync(0xFFFFFFFFu, cnt >= BUCK_FLUSH)) {
                // Replay staged items in scan order through the EXACT serial
                // strict-'<' chain (round-5/9/11 passing semantics). Replaying
                // a superset of qualifying candidates is a no-op for the
                // non-qualifying ones, so stale-tau staging is bit-exact.
                for (int u = 0; u < cnt; ++u) {
                    float dv = s_bdk[u * TPB + tid];
                    if (dv < bd[KNN - 1]) {
                        int id = s_bik[u * TPB + tid];
#pragma unroll
                        for (int k = 0; k < KNN; ++k) {
                            if (dv < bd[k]) {
                                float td = bd[k]; bd[k] = dv; dv = td;
                                int   ti = bi[k]; bi[k] = id; id = ti;
                            }
                        }
                    }
                }
                cnt = 0;
                tau = bd[KNN - 1];
            }
        }
    }
    // Flush remaining staged candidates.
    for (int u = 0; u < cnt; ++u) {
        float dv = s_bdk[u * TPB + tid];
        if (dv < bd[KNN - 1]) {
            int id = s_bik[u * TPB + tid];
#pragma unroll
            for (int k = 0; k < KNN; ++k) {
                if (dv < bd[k]) {
                    float td = bd[k]; bd[k] = dv; dv = td;
                    int   ti = bi[k]; bi[k] = id; id = ti;
                }
            }
        }
    }

    // Publish partial lists.
#pragma unroll
    for (int k = 0; k < KNN; ++k) {
        s_md[tid * KNN + k] = bd[k];
        s_mi[tid * KNN + k] = bi[k];
    }
    __syncthreads();

    // Threads 0..31 merge their query's four sorted lists sequentially.
    // On equal d2 the lower group wins (its indices are all lower) —
    // same tie rule as the passing round-9/11 merges.
    if (tid < QPB) {
        float m1d[KNN]; int m1i[KNN];
        // merge group 0 with group 1
        {
            const int a = (0 * QPB + tid) * KNN;
            const int b = (1 * QPB + tid) * KNN;
            int ia = 0, ib = 0;
#pragma unroll
            for (int k = 0; k < KNN; ++k) {
                const float da = s_md[a + ia];
                const float db = s_md[b + ib];
                if (da <= db) { m1d[k] = da; m1i[k] = s_mi[a + ia]; ++ia; }
                else          { m1d[k] = db; m1i[k] = s_mi[b + ib]; ++ib; }
            }
        }
        float m2d[KNN]; int m2i[KNN];
        // merge (0,1) with group 2
        {
            const int b = (2 * QPB + tid) * KNN;
            int ia = 0, ib = 0;
#pragma unroll
            for (int k = 0; k < KNN; ++k) {
                const float da = m1d[ia];
                const float db = s_md[b + ib];
                if (da <= db) { m2d[k] = da; m2i[k] = m1i[ia]; ++ia; }
                else          { m2d[k] = db; m2i[k] = s_mi[b + ib]; ++ib; }
            }
        }
        int fi[KNN];
        // merge (0,1,2) with group 3
        {
            const int b = (3 * QPB + tid) * KNN;
            int ia = 0, ib = 0;
#pragma unroll
            for (int k = 0; k < KNN; ++k) {
                const float da = m2d[ia];
                const float db = s_md[b + ib];
                if (da <= db) { fi[k] = m2i[ia]; ++ia; }
                else          { fi[k] = s_mi[b + ib]; ++ib; }
            }
        }

        // ---- gather features and apply collapsed linear head ----
        const int qq  = blockIdx.x * QPB + tid;
        const int bb2 = qq >> 13;
        const int ii  = qq & (NPTS - 1);
        const float* __restrict__ bpos2 = pos + (size_t)bb2 * NPTS * 3;
        const float* __restrict__ bvel2 = vel + (size_t)bb2 * NPTS * 3;
        const float qx2 = bpos2[ii * 3 + 0];
        const float qy2 = bpos2[ii * 3 + 1];
        const float qz2 = bpos2[ii * 3 + 2];

        float acc[6];
#pragma unroll
        for (int c = 0; c < 6; ++c) acc[c] = s_bc[c];

        // rows 0..32: neighbor velocities (incl. self, rank order)
#pragma unroll
        for (int r = 0; r < KNN; ++r) {
            const int j = fi[r];
            const float vx = bvel2[j * 3 + 0];
            const float vy = bvel2[j * 3 + 1];
            const float vz = bvel2[j * 3 + 2];
            const int row = 3 * r;
#pragma unroll
            for (int c = 0; c < 6; ++c) {
                acc[c] = fmaf(vx, s_Wc[(row + 0) * 6 + c], acc[c]);
                acc[c] = fmaf(vy, s_Wc[(row + 1) * 6 + c], acc[c]);
                acc[c] = fmaf(vz, s_Wc[(row + 2) * 6 + c], acc[c]);
            }
        }
        // rows 33..62: neighbor position offsets (excl. self)
#pragma unroll
        for (int r = 1; r < KNN; ++r) {
            const int j = fi[r];
            const float ox = bpos2[j * 3 + 0] - qx2;
            const float oy = bpos2[j * 3 + 1] - qy2;
            const float oz = bpos2[j * 3 + 2] - qz2;
            const int row = 33 + 3 * (r - 1);
#pragma unroll
            for (int c = 0; c < 6; ++c) {
                acc[c] = fmaf(ox, s_Wc[(row + 0) * 6 + c], acc[c]);
                acc[c] = fmaf(oy, s_Wc[(row + 1) * 6 + c], acc[c]);
                acc[c] = fmaf(oz, s_Wc[(row + 2) * 6 + c], acc[c]);
            }
        }
        // rows 63..65: init_config
        {
            const float i0 = initc[bb2 * 3 + 0];
            const float i1 = initc[bb2 * 3 + 1];
            const float i2 = initc[bb2 * 3 + 2];
#pragma unroll
            for (int c = 0; c < 6; ++c) {
                acc[c] = fmaf(i0, s_Wc[63 * 6 + c], acc[c]);
                acc[c] = fmaf(i1, s_Wc[64 * 6 + c], acc[c]);
                acc[c] = fmaf(i2, s_Wc[65 * 6 + c], acc[c]);
            }
        }

        float* o = out + (size_t)qq * 6;
        o[0] = acc[0] + qx2;
        o[1] = acc[1] + qy2;
        o[2] = acc[2] + qz2;
        o[3] = acc[3];
        o[4] = acc[4];
        o[5] = acc[5];
    }
}

// ---------------------------------------------------------------------------
extern "C" void kernel_launch(void* const* d_in, const int* in_sizes, int n_in,
                              void* d_out, int out_size)
{
    const float* position = (const float*)d_in[0];
    const float* velocity = (const float*)d_in[1];
    const float* initcfg  = (const float*)d_in[2];
    const float* W1 = (const float*)d_in[3];
    const float* b1 = (const float*)d_in[4];
    const float* W2 = (const float*)d_in[5];
    const float* b2 = (const float*)d_in[6];
    const float* W3 = (const float*)d_in[7];
    const float* b3 = (const float*)d_in[8];
    float* out = (float*)d_out;

    combine_weights_kernel<<<1, 256>>>(W1, b1, W2, b2, W3, b3);

    const int total = BATCH * NPTS;           // 16384 queries
    knn_mlp_kernel<<<total / QPB, TPB>>>(position, velocity, initcfg, out);
}

// round 15
// speedup vs baseline: 1.8674x; 1.0272x over previous
#include <cuda_runtime.h>
#include <cuda_bf16.h>
#include <math_constants.h>

// Problem constants
#define BATCH   2
#define NPTS    8192
#define KNN     11        // k+1 including self
#define LEN_IN  66        // 3*11 + 3*10 + 3
#define TPB     128
#define NGROUP  4         // split-K over candidates
#define QPB     (TPB / NGROUP)        // 32 queries per block
#define GRANGE  (NPTS / NGROUP)       // 2048 candidates per group
#define CHUNK   256                   // candidates per group per smem iteration
#define NPAIR   (CHUNK / 2)           // 128 candidate pairs per group chunk
#define NITER   (GRANGE / CHUNK)      // 8
#define BUCK_CAP    24                // per-thread staging slots
#define BUCK_FLUSH  8                 // flush when any lane reaches this

typedef unsigned long long ull;

// Collapsed weights (device scratch; no allocations allowed)
__device__ float g_W12[LEN_IN * 16];
__device__ float g_Wc [LEN_IN * 6];
__device__ float g_bc [6];

// ---- packed f32x2 helpers (each lane is bit-identical to the scalar op) ----
__device__ __forceinline__ ull mul2(ull a, ull b) {
    ull r; asm("mul.rn.f32x2 %0, %1, %2;" : "=l"(r) : "l"(a), "l"(b)); return r;
}
__device__ __forceinline__ ull add2(ull a, ull b) {
    ull r; asm("add.rn.f32x2 %0, %1, %2;" : "=l"(r) : "l"(a), "l"(b)); return r;
}
__device__ __forceinline__ ull fma2(ull a, ull b, ull c) {
    ull r; asm("fma.rn.f32x2 %0, %1, %2, %3;" : "=l"(r) : "l"(a), "l"(b), "l"(c)); return r;
}
__device__ __forceinline__ ull pack2(float lo, float hi) {
    return (ull)__float_as_uint(lo) | ((ull)__float_as_uint(hi) << 32);
}
__device__ __forceinline__ void unpack2(ull v, float& lo, float& hi) {
    asm("mov.b64 {%0, %1}, %2;" : "=f"(lo), "=f"(hi) : "l"(v));
}

// ---------------------------------------------------------------------------
// Prologue: collapse W1@W2@W3 and the bias chain (tiny, one block).
// The reference MLP has no activation functions, so the whole head is affine:
//   pred = feats @ (W1@W2@W3) + ((b1@W2 + b2)@W3 + b3)
// ---------------------------------------------------------------------------
__global__ void combine_weights_kernel(const float* __restrict__ W1,
                                       const float* __restrict__ b1,
                                       const float* __restrict__ W2,
                                       const float* __restrict__ b2,
                                       const float* __restrict__ W3,
                                       const float* __restrict__ b3)
{
    int t = threadIdx.x;
    // W12 = W1[66,32] @ W2[32,16]
    for (int e = t; e < LEN_IN * 16; e += blockDim.x) {
        int r = e / 16, c = e % 16;
        float s = 0.f;
        for (int k = 0; k < 32; ++k) s += W1[r * 32 + k] * W2[k * 16 + c];
        g_W12[e] = s;
    }
    __syncthreads();
    // Wc = W12[66,16] @ W3[16,6]
    for (int e = t; e < LEN_IN * 6; e += blockDim.x) {
        int r = e / 6, c = e % 6;
        float s = 0.f;
        for (int k = 0; k < 16; ++k) s += g_W12[r * 16 + k] * W3[k * 6 + c];
        g_Wc[e] = s;
    }
    // bc = ((b1@W2)+b2)@W3 + b3
    if (t < 6) {
        float s = b3[t];
        for (int k = 0; k < 16; ++k) {
            float tb = b2[k];
            for (int m = 0; m < 32; ++m) tb += b1[m] * W2[m * 16 + k];
            s += tb * W3[k * 6 + t];
        }
        g_bc[t] = s;
    }
}

// ---------------------------------------------------------------------------
// Main fused kernel: split-K brute-force kNN (top-11 by d2) with packed-pair
// distance math, pair-level guard, staged inserts (slot-major buckets) +
// exact 4-way merge + gather + collapsed linear head.
//   Block = 32 queries x 4 candidate groups (128 threads).
// ---------------------------------------------------------------------------
__global__ void __launch_bounds__(TPB)
knn_mlp_kernel(const float* __restrict__ pos,
               const float* __restrict__ vel,
               const float* __restrict__ initc,
               float* __restrict__ out)
{
    // Tile in pair-packed SoA: sXY[p] = ((x0,x1),(y0,y1)), sZW[p] = ((z0,z1),(w0,w1))
    __shared__ ulonglong2 sXY[NGROUP * NPAIR];     // 8KB
    __shared__ ulonglong2 sZW[NGROUP * NPAIR];     // 8KB
    __shared__ float  s_bdk[BUCK_CAP * TPB];       // staged d2, slot-major (12KB)
    __shared__ int    s_bik[BUCK_CAP * TPB];       // staged idx, slot-major (12KB)
    __shared__ float  s_md[TPB * KNN];             // partial top-11 distances
    __shared__ int    s_mi[TPB * KNN];             // partial top-11 indices
    __shared__ float  s_Wc[LEN_IN * 6];
    __shared__ float  s_bc[6];

    const int tid  = threadIdx.x;
    const int grp  = tid >> 5;                     // 0..3  (== warp id)
    const int qloc = tid & (QPB - 1);              // query within block
    const int q    = blockIdx.x * QPB + qloc;      // global query id
    const int bb   = q >> 13;                      // q / 8192 (batch)
    const int i    = q & (NPTS - 1);

    const float* __restrict__ bpos = pos + (size_t)bb * NPTS * 3;
    const float* __restrict__ bvel = vel + (size_t)bb * NPTS * 3;

    for (int t = tid; t < LEN_IN * 6; t += TPB) s_Wc[t] = g_Wc[t];
    if (tid < 6) s_bc[tid] = g_bc[tid];

    // Query point; sq computed with the SAME op sequence as the tile loader so
    // the self-distance is exactly 0 (round-5 passing recipe, unchanged).
    const float qx = bpos[i * 3 + 0];
    const float qy = bpos[i * 3 + 1];
    const float qz = bpos[i * 3 + 2];
    float qs = qx * qx; qs = fmaf(qy, qy, qs); qs = fmaf(qz, qz, qs);

    // Packed query constants
    const ull qxx = pack2(qx, qx);
    const ull qyy = pack2(qy, qy);
    const ull qzz = pack2(qz, qz);
    const ull qss = pack2(qs, qs);
    const ull m22 = pack2(-2.0f, -2.0f);

    // Per-group sorted top-11 (ascending), register-resident.
    float bd[KNN];
    int   bi[KNN];
#pragma unroll
    for (int k = 0; k < KNN; ++k) { bd[k] = CUDART_INF_F; bi[k] = 0; }

    int   cnt = 0;
    float tau = CUDART_INF_F;

    const ulonglong2* __restrict__ myXY = sXY + grp * NPAIR;
    const ulonglong2* __restrict__ myZW = sZW + grp * NPAIR;

    for (int it = 0; it < NITER; ++it) {
        __syncthreads();
        // Cooperative load of all groups' chunks in pair-packed form.
        for (int t = tid; t < NGROUP * NPAIR; t += TPB) {
            const int g  = t >> 7;                        // t / NPAIR
            const int pr = t & (NPAIR - 1);
            const int j0 = g * GRANGE + it * CHUNK + 2 * pr;  // global cand id
            const float x0 = bpos[j0 * 3 + 0];
            const float y0 = bpos[j0 * 3 + 1];
            const float z0 = bpos[j0 * 3 + 2];
            const float x1 = bpos[j0 * 3 + 3];
            const float y1 = bpos[j0 * 3 + 4];
            const float z1 = bpos[j0 * 3 + 5];
            float s0 = x0 * x0; s0 = fmaf(y0, y0, s0); s0 = fmaf(z0, z0, s0);
            float s1 = x1 * x1; s1 = fmaf(y1, y1, s1); s1 = fmaf(z1, z1, s1);
            sXY[t] = make_ulonglong2(pack2(x0, x1), pack2(y0, y1));
            sZW[t] = make_ulonglong2(pack2(z0, z1), pack2(s0, s1));
        }
        __syncthreads();

        const int idxbase = grp * GRANGE + it * CHUNK;
        for (int ptb = 0; ptb < NPAIR; ptb += 8) {
#pragma unroll
            for (int v = 0; v < 8; ++v) {
                const int pt = ptb + v;
                const ulonglong2 xy = myXY[pt];
                const ulonglong2 zw = myZW[pt];
                // Packed distance: lanes identical to the scalar recipe
                // d = qx*x; d = fma(qy,y,d); d = fma(qz,z,d);
                // d2 = fma(-2, d, qs + sq)
                ull dd = mul2(qxx, xy.x);
                dd = fma2(qyy, xy.y, dd);
                dd = fma2(qzz, zw.x, dd);
                const ull tt = add2(qss, zw.y);
                const ull rr = fma2(m22, dd, tt);
                float d2lo, d2hi;
                unpack2(rr, d2lo, d2hi);
                // Pair-level guard: staging ops only execute on the rare
                // qualifying path. Membership test and scan order (lo then
                // hi) are identical to the per-candidate version.
                if (fminf(d2lo, d2hi) < tau) {
                    if (d2lo < tau) {
                        s_bdk[cnt * TPB + tid] = d2lo;
                        s_bik[cnt * TPB + tid] = idxbase + 2 * pt;
                        ++cnt;
                    }
                    if (d2hi < tau) {
                        s_bdk[cnt * TPB + tid] = d2hi;
                        s_bik[cnt * TPB + tid] = idxbase + 2 * pt + 1;
                        ++cnt;
                    }
                }
            }
            // Warp-coherent flush when any lane's bucket reaches threshold.
            // (<=16 appends between checks; 7 + 16 = 23 <= BUCK_CAP=24.)
            if (__ballot_sync(0xFFFFFFFFu, cnt >= BUCK_FLUSH)) {
                // Replay staged items in scan order through the EXACT serial
                // strict-'<' chain (round-5/9/11 passing semantics). Replaying
                // a superset of qualifying candidates is a no-op for the
                // non-qualifying ones, so stale-tau staging is bit-exact.
                for (int u = 0; u < cnt; ++u) {
                    float dv = s_bdk[u * TPB + tid];
                    if (dv < bd[KNN - 1]) {
                        int id = s_bik[u * TPB + tid];
#pragma unroll
                        for (int k = 0; k < KNN; ++k) {
                            if (dv < bd[k]) {
                                float td = bd[k]; bd[k] = dv; dv = td;
                                int   ti = bi[k]; bi[k] = id; id = ti;
                            }
                        }
                    }
                }
                cnt = 0;
                tau = bd[KNN - 1];
            }
        }
    }
    // Flush remaining staged candidates.
    for (int u = 0; u < cnt; ++u) {
        float dv = s_bdk[u * TPB + tid];
        if (dv < bd[KNN - 1]) {
            int id = s_bik[u * TPB + tid];
#pragma unroll
            for (int k = 0; k < KNN; ++k) {
                if (dv < bd[k]) {
                    float td = bd[k]; bd[k] = dv; dv = td;
                    int   ti = bi[k]; bi[k] = id; id = ti;
                }
            }
        }
    }

    // Publish partial lists.
#pragma unroll
    for (int k = 0; k < KNN; ++k) {
        s_md[tid * KNN + k] = bd[k];
        s_mi[tid * KNN + k] = bi[k];
    }
    __syncthreads();

    // Threads 0..31 merge their query's four sorted lists sequentially.
    // On equal d2 the lower group wins (its indices are all lower) —
    // same tie rule as the passing round-9/11/14 merges.
    if (tid < QPB) {
        float m1d[KNN]; int m1i[KNN];
        // merge group 0 with group 1
        {
            const int a = (0 * QPB + tid) * KNN;
            const int b = (1 * QPB + tid) * KNN;
            int ia = 0, ib = 0;
#pragma unroll
            for (int k = 0; k < KNN; ++k) {
                const float da = s_md[a + ia];
                const float db = s_md[b + ib];
                if (da <= db) { m1d[k] = da; m1i[k] = s_mi[a + ia]; ++ia; }
                else          { m1d[k] = db; m1i[k] = s_mi[b + ib]; ++ib; }
            }
        }
        float m2d[KNN]; int m2i[KNN];
        // merge (0,1) with group 2
        {
            const int b = (2 * QPB + tid) * KNN;
            int ia = 0, ib = 0;
#pragma unroll
            for (int k = 0; k < KNN; ++k) {
                const float da = m1d[ia];
                const float db = s_md[b + ib];
                if (da <= db) { m2d[k] = da; m2i[k] = m1i[ia]; ++ia; }
                else          { m2d[k] = db; m2i[k] = s_mi[b + ib]; ++ib; }
            }
        }
        int fi[KNN];
        // merge (0,1,2) with group 3
        {
            const int b = (3 * QPB + tid) * KNN;
            int ia = 0, ib = 0;
#pragma unroll
            for (int k = 0; k < KNN; ++k) {
                const float da = m2d[ia];
                const float db = s_md[b + ib];
                if (da <= db) { fi[k] = m2i[ia]; ++ia; }
                else          { fi[k] = s_mi[b + ib]; ++ib; }
            }
        }

        // ---- gather features and apply collapsed linear head ----
        const int qq  = blockIdx.x * QPB + tid;
        const int bb2 = qq >> 13;
        const int ii  = qq & (NPTS - 1);
        const float* __restrict__ bpos2 = pos + (size_t)bb2 * NPTS * 3;
        const float* __restrict__ bvel2 = vel + (size_t)bb2 * NPTS * 3;
        const float qx2 = bpos2[ii * 3 + 0];
        const float qy2 = bpos2[ii * 3 + 1];
        const float qz2 = bpos2[ii * 3 + 2];

        float acc[6];
#pragma unroll
        for (int c = 0; c < 6; ++c) acc[c] = s_bc[c];

        // rows 0..32: neighbor velocities (incl. self, rank order)
#pragma unroll
        for (int r = 0; r < KNN; ++r) {
            const int j = fi[r];
            const float vx = bvel2[j * 3 + 0];
            const float vy = bvel2[j * 3 + 1];
            const float vz = bvel2[j * 3 + 2];
            const int row = 3 * r;
#pragma unroll
            for (int c = 0; c < 6; ++c) {
                acc[c] = fmaf(vx, s_Wc[(row + 0) * 6 + c], acc[c]);
                acc[c] = fmaf(vy, s_Wc[(row + 1) * 6 + c], acc[c]);
                acc[c] = fmaf(vz, s_Wc[(row + 2) * 6 + c], acc[c]);
            }
        }
        // rows 33..62: neighbor position offsets (excl. self)
#pragma unroll
        for (int r = 1; r < KNN; ++r) {
            const int j = fi[r];
            const float ox = bpos2[j * 3 + 0] - qx2;
            const float oy = bpos2[j * 3 + 1] - qy2;
            const float oz = bpos2[j * 3 + 2] - qz2;
            const int row = 33 + 3 * (r - 1);
#pragma unroll
            for (int c = 0; c < 6; ++c) {
                acc[c] = fmaf(ox, s_Wc[(row + 0) * 6 + c], acc[c]);
                acc[c] = fmaf(oy, s_Wc[(row + 1) * 6 + c], acc[c]);
                acc[c] = fmaf(oz, s_Wc[(row + 2) * 6 + c], acc[c]);
            }
        }
        // rows 63..65: init_config
        {
            const float i0 = initc[bb2 * 3 + 0];
            const float i1 = initc[bb2 * 3 + 1];
            const float i2 = initc[bb2 * 3 + 2];
#pragma unroll
            for (int c = 0; c < 6; ++c) {
                acc[c] = fmaf(i0, s_Wc[63 * 6 + c], acc[c]);
                acc[c] = fmaf(i1, s_Wc[64 * 6 + c], acc[c]);
                acc[c] = fmaf(i2, s_Wc[65 * 6 + c], acc[c]);
            }
        }

        float* o = out + (size_t)qq * 6;
        o[0] = acc[0] + qx2;
        o[1] = acc[1] + qy2;
        o[2] = acc[2] + qz2;
        o[3] = acc[3];
        o[4] = acc[4];
        o[5] = acc[5];
    }
}

// ---------------------------------------------------------------------------
extern "C" void kernel_launch(void* const* d_in, const int* in_sizes, int n_in,
                              void* d_out, int out_size)
{
    const float* position = (const float*)d_in[0];
    const float* velocity = (const float*)d_in[1];
    const float* initcfg  = (const float*)d_in[2];
    const float* W1 = (const float*)d_in[3];
    const float* b1 = (const float*)d_in[4];
    const float* W2 = (const float*)d_in[5];
    const float* b2 = (const float*)d_in[6];
    const float* W3 = (const float*)d_in[7];
    const float* b3 = (const float*)d_in[8];
    float* out = (float*)d_out;

    combine_weights_kernel<<<1, 256>>>(W1, b1, W2, b2, W3, b3);

    const int total = BATCH * NPTS;           // 16384 queries
    knn_mlp_kernel<<<total / QPB, TPB>>>(position, velocity, initcfg, out);
}